// round 14
// baseline (speedup 1.0000x reference)
#include <cuda_runtime.h>
#include <cuda_bf16.h>
#include <cuda_fp16.h>
#include <cstdint>

#define N_NODES 50000
#define IN_DIM 2000
#define IN_DIM_PAD 2048
#define GRAPH_DIM 512
#define HIDDEN_DIM 256
#define LATENT_DIM 64
#define N_EDGES 1600000
#define BN_EPS 1e-5f

// Scratch (device globals; allocation is forbidden)
__device__ __half g_h16[(size_t)N_NODES * GRAPH_DIM];   // GEMM1 out (half), SpMM in
__device__ float g_agg[(size_t)N_NODES * GRAPH_DIM];    // SpMM out (fp32)
__device__ float g_h1[(size_t)N_NODES * HIDDEN_DIM];    // GEMM2 out (fp32, pre-BN1)
__device__ float g_stats0[2 * GRAPH_DIM];
__device__ float g_stats1[2 * HIDDEN_DIM];
__device__ float g_sc0[GRAPH_DIM], g_sh0[GRAPH_DIM];
__device__ float g_sc1[HIDDEN_DIM], g_sh1[HIDDEN_DIM];
// CSR scratch
__device__ int g_rowcnt[N_NODES];
__device__ int g_rowstart[N_NODES + 1];
__device__ int g_cursor[N_NODES];
__device__ int2 g_edges[N_EDGES];
// fp16 transposed weights
__device__ __half g_WgT_f16[(size_t)GRAPH_DIM * IN_DIM_PAD];
__device__ __half g_W1T_f16[(size_t)HIDDEN_DIM * GRAPH_DIM];
__device__ __half g_WlatT_f16[(size_t)128 * HIDDEN_DIM];
__device__ float g_blat[128];

static inline int cdiv(int a, int b) { return (a + b - 1) / b; }

// ---------------------------------------------------------------------------
// PTX helpers
// ---------------------------------------------------------------------------
__device__ __forceinline__ uint32_t smem_u32(const void* p) {
    uint32_t a;
    asm("{ .reg .u64 t; cvta.to.shared.u64 t, %1; cvt.u32.u64 %0, t; }" : "=r"(a) : "l"(p));
    return a;
}
__device__ __forceinline__ void ldsm4(uint32_t* d, uint32_t addr) {
    asm volatile("ldmatrix.sync.aligned.m8n8.x4.shared.b16 {%0,%1,%2,%3}, [%4];"
                 : "=r"(d[0]), "=r"(d[1]), "=r"(d[2]), "=r"(d[3]) : "r"(addr));
}
__device__ __forceinline__ void mma_fp16(float* c, const uint32_t* a, const uint32_t* b) {
    asm volatile(
        "mma.sync.aligned.m16n8k16.row.col.f32.f16.f16.f32 "
        "{%0,%1,%2,%3}, {%4,%5,%6,%7}, {%8,%9}, {%0,%1,%2,%3};"
        : "+f"(c[0]), "+f"(c[1]), "+f"(c[2]), "+f"(c[3])
        : "r"(a[0]), "r"(a[1]), "r"(a[2]), "r"(a[3]), "r"(b[0]), "r"(b[1]));
}
__device__ __forceinline__ void cp16(uint32_t dst, const void* src) {
    asm volatile("cp.async.cg.shared.global [%0], [%1], 16;" :: "r"(dst), "l"(src));
}
#define CP_COMMIT() asm volatile("cp.async.commit_group;" ::: "memory")
#define CP_WAIT0()  asm volatile("cp.async.wait_group 0;" ::: "memory")

__device__ __forceinline__ uint32_t pack_h2(__half lo, __half hi) {
    return ((uint32_t)__half_as_ushort(hi) << 16) | (uint32_t)__half_as_ushort(lo);
}
__device__ __forceinline__ float softplus_f(float x) {
    return fmaxf(x, 0.f) + log1pf(expf(-fabsf(x)));
}

// ---------------------------------------------------------------------------
// Weight prep: W[K,Nc] fp32 -> T[Nc][Kpad] fp16 (transposed)
// ---------------------------------------------------------------------------
__global__ void conv_w_fp16(const float* __restrict__ W, __half* __restrict__ T,
                            int K, int Nc, int Kpad)
{
    int idx = blockIdx.x * blockDim.x + threadIdx.x;
    if (idx >= Nc * Kpad) return;
    int n = idx / Kpad;
    int k = idx % Kpad;
    float v = (k < K) ? W[(size_t)k * Nc + n] : 0.f;
    T[idx] = __float2half(v);
}

__global__ void concat_bias(const float* __restrict__ b21, const float* __restrict__ b22,
                            float* __restrict__ blat)
{
    int t = threadIdx.x;
    if (t < 64) blat[t] = b21[t];
    else if (t < 128) blat[t] = b22[t - 64];
}

// ---------------------------------------------------------------------------
// fp16 tensor-core GEMM, K-chunk 64, 512 threads (16 warps, warptile 32 x BN/4).
// ---------------------------------------------------------------------------
#define GBM 128
#define GK 64
#define RB 144
#define ATILE (GBM * RB)   // 18432

template <int BN>
__global__ void __launch_bounds__(512)
fp16_gemm(const float* __restrict__ A, int lda, int Kvalid, int Kpad,
          const __half* __restrict__ B,
          const float* __restrict__ bias, void* __restrict__ Cv, int ldc, int M,
          int outmode, const float* __restrict__ Ascale, const float* __restrict__ Ashift)
{
    constexpr int BTILE = BN * RB;
    constexpr int STAGE = ATILE + BTILE;
    constexpr int NT = BN / 32;
    constexpr int NLD = BN / 64;
    constexpr int BCH = BN * GK / 4096;

    extern __shared__ char sm[];
    const uint32_t smb = smem_u32(sm);

    const int tid = threadIdx.x;
    const int lane = tid & 31;
    const int wid = tid >> 5;
    const int warpM = wid >> 2;
    const int warpN = wid & 3;
    const int rowBase = blockIdx.y * GBM;
    const int colBase = blockIdx.x * BN;
    const int nIter = Kpad / GK;
    const bool fuse = (Ascale != nullptr);

    float acc[2][NT][4];
#pragma unroll
    for (int i = 0; i < 2; i++)
#pragma unroll
        for (int j = 0; j < NT; j++)
#pragma unroll
            for (int v = 0; v < 4; v++) acc[i][j][v] = 0.f;

    float4 av[4];
    int arow[4], akq[4];
#pragma unroll
    for (int q = 0; q < 4; q++) {
        int qi = tid + q * 512;
        arow[q] = qi >> 4;
        akq[q] = qi & 15;
    }

    auto loadA = [&](int it) {
        int k0 = it * GK;
#pragma unroll
        for (int q = 0; q < 4; q++) {
            int gr = rowBase + arow[q];
            int k = k0 + akq[q] * 4;
            float4 v = make_float4(0.f, 0.f, 0.f, 0.f);
            if (gr < M) {
                const float* src = A + (size_t)gr * lda + k;
                if (k + 3 < Kvalid) {
                    v = *(const float4*)src;
                    if (fuse) {
                        v.x = softplus_f(v.x * __ldg(&Ascale[k + 0]) + __ldg(&Ashift[k + 0]));
                        v.y = softplus_f(v.y * __ldg(&Ascale[k + 1]) + __ldg(&Ashift[k + 1]));
                        v.z = softplus_f(v.z * __ldg(&Ascale[k + 2]) + __ldg(&Ashift[k + 2]));
                        v.w = softplus_f(v.w * __ldg(&Ascale[k + 3]) + __ldg(&Ashift[k + 3]));
                    }
                } else if (k < Kvalid) {
                    float* vp = &v.x;
#pragma unroll
                    for (int j = 0; j < 4; j++) {
                        if (k + j < Kvalid) {
                            float t = src[j];
                            if (fuse)
                                t = softplus_f(t * __ldg(&Ascale[k + j]) + __ldg(&Ashift[k + j]));
                            vp[j] = t;
                        }
                    }
                }
            }
            av[q] = v;
        }
    };

    auto stsA = [&](int stage) {
        char* sp = sm + stage * STAGE;
#pragma unroll
        for (int q = 0; q < 4; q++) {
            float4 v = av[q];
            __half h0 = __float2half(v.x);
            __half h1 = __float2half(v.y);
            __half h2 = __float2half(v.z);
            __half h3 = __float2half(v.w);
            uint2 hp = make_uint2(pack_h2(h0, h1), pack_h2(h2, h3));
            int off = arow[q] * RB + akq[q] * 8;
            *(uint2*)(sp + off) = hp;
        }
    };

    auto cpB = [&](int it, int stage) {
        int k0 = it * GK;
#pragma unroll
        for (int q = 0; q < BCH; q++) {
            int ci = tid + q * 512;
            int row = ci >> 3;
            int c = ci & 7;
            const __half* src = B + (size_t)(colBase + row) * Kpad + k0 + c * 8;
            uint32_t dst = smb + stage * STAGE + ATILE + row * RB + c * 16;
            cp16(dst, src);
        }
    };

    const uint32_t aLaneOff = (uint32_t)((lane & 15) * RB + ((lane >> 4) << 4));
    const uint32_t bLaneOff = (uint32_t)(((lane & 7) + ((lane & 16) >> 1)) * RB
                                         + (((lane >> 3) & 1) << 4));

    loadA(0);
    cpB(0, 0);
    CP_COMMIT();
    stsA(0);

    for (int it = 0; it < nIter; ++it) {
        const int cur = it & 1;
        const int nxt = cur ^ 1;
        const bool more = (it + 1 < nIter);
        if (more) loadA(it + 1);
        CP_WAIT0();
        __syncthreads();
        if (more) {
            stsA(nxt);
            cpB(it + 1, nxt);
            CP_COMMIT();
        }

        const uint32_t aBase = smb + cur * STAGE + warpM * 32 * RB + aLaneOff;
        const uint32_t bBase = smb + cur * STAGE + ATILE + warpN * (BN / 4) * RB + bLaneOff;
#pragma unroll
        for (int ks = 0; ks < GK / 16; ks++) {
            const uint32_t kb = ks * 32;
            uint32_t bF[NLD][4], aH[2][4];
#pragma unroll
            for (int g = 0; g < NLD; g++) ldsm4(bF[g], bBase + g * 16 * RB + kb);
#pragma unroll
            for (int mt = 0; mt < 2; mt++) ldsm4(aH[mt], aBase + mt * 16 * RB + kb);
#pragma unroll
            for (int mt = 0; mt < 2; mt++)
#pragma unroll
                for (int nt = 0; nt < NT; nt++)
                    mma_fp16(acc[mt][nt], aH[mt], &bF[nt >> 1][(nt & 1) * 2]);
        }
    }

    const int r0 = rowBase + warpM * 32 + (lane >> 2);
    const int c0 = colBase + warpN * (BN / 4) + (lane & 3) * 2;
#pragma unroll
    for (int mt = 0; mt < 2; mt++) {
#pragma unroll
        for (int nt = 0; nt < NT; nt++) {
            int r = r0 + mt * 16;
            int c = c0 + nt * 8;
            float b0 = bias[c], b1 = bias[c + 1];
            float v0 = acc[mt][nt][0] + b0;
            float v1 = acc[mt][nt][1] + b1;
            float v2 = acc[mt][nt][2] + b0;
            float v3 = acc[mt][nt][3] + b1;
            if (outmode == 0) {
                float* C = (float*)Cv;
                if (r < M) *(float2*)&C[(size_t)r * ldc + c] = make_float2(v0, v1);
                if (r + 8 < M) *(float2*)&C[(size_t)(r + 8) * ldc + c] = make_float2(v2, v3);
            } else if (outmode == 1) {
                float* C = (float*)Cv;
                float* base = (c < 64) ? C + c : C + (size_t)N_NODES * 64 + (c - 64);
                if (r < M) *(float2*)&base[(size_t)r * 64] = make_float2(v0, v1);
                if (r + 8 < M) *(float2*)&base[(size_t)(r + 8) * 64] = make_float2(v2, v3);
            } else {
                __half* C = (__half*)Cv;
                if (r < M) *(__half2*)&C[(size_t)r * ldc + c] = __floats2half2_rn(v0, v1);
                if (r + 8 < M) *(__half2*)&C[(size_t)(r + 8) * ldc + c] = __floats2half2_rn(v2, v3);
            }
        }
    }
}

// ---------------------------------------------------------------------------
// Zero kernels
// ---------------------------------------------------------------------------
__global__ void zero_kernel(float4* __restrict__ p, long long n4) {
    long long i = (long long)blockIdx.x * blockDim.x + threadIdx.x;
    long long stride = (long long)gridDim.x * blockDim.x;
    float4 z = make_float4(0.f, 0.f, 0.f, 0.f);
    for (; i < n4; i += stride) p[i] = z;
}
__global__ void zero_int(int* __restrict__ p, int n) {
    int i = blockIdx.x * blockDim.x + threadIdx.x;
    if (i < n) p[i] = 0;
}

// ---------------------------------------------------------------------------
// CSR build: histogram -> scan -> scatter
// ---------------------------------------------------------------------------
__global__ void csr_hist(const int* __restrict__ rows, int* __restrict__ cnt) {
    int e = blockIdx.x * blockDim.x + threadIdx.x;
    if (e < N_EDGES) atomicAdd(&cnt[rows[e]], 1);
}

__global__ void __launch_bounds__(1024)
csr_scan(const int* __restrict__ cnt, int* __restrict__ rowstart, int* __restrict__ cursor)
{
    __shared__ int warpsum[32];
    const int t = threadIdx.x;
    const int CH = (N_NODES + 1023) / 1024;
    const int base = t * CH;

    int s = 0;
    for (int i = 0; i < CH; i++) {
        int idx = base + i;
        if (idx < N_NODES) s += cnt[idx];
    }
    int lane = t & 31, w = t >> 5;
    int v = s;
#pragma unroll
    for (int o = 1; o < 32; o <<= 1) {
        int n = __shfl_up_sync(0xffffffffu, v, o);
        if (lane >= o) v += n;
    }
    if (lane == 31) warpsum[w] = v;
    __syncthreads();
    if (w == 0) {
        int x = warpsum[lane];
#pragma unroll
        for (int o = 1; o < 32; o <<= 1) {
            int n = __shfl_up_sync(0xffffffffu, x, o);
            if (lane >= o) x += n;
        }
        warpsum[lane] = x;
    }
    __syncthreads();
    int run = v - s + (w > 0 ? warpsum[w - 1] : 0);
    for (int i = 0; i < CH; i++) {
        int idx = base + i;
        if (idx < N_NODES) {
            rowstart[idx] = run;
            cursor[idx] = run;
            run += cnt[idx];
        }
    }
    if (t == 1023) rowstart[N_NODES] = N_EDGES;
}

__global__ void csr_scatter(const int* __restrict__ rows, const int* __restrict__ cols,
                            const float* __restrict__ vals, int* __restrict__ cursor,
                            int2* __restrict__ edges)
{
    int e = blockIdx.x * blockDim.x + threadIdx.x;
    if (e >= N_EDGES) return;
    int r = rows[e];
    int p = atomicAdd(&cursor[r], 1);
    edges[p] = make_int2(cols[e], __float_as_int(vals[e]));
}

// ---------------------------------------------------------------------------
// CSR SpMM over half h, uint4 gathers (8 halves/thread, 64 threads/row).
// 128-thread block: sub 0/1 split each staged 128-edge tile into halves,
// processing up to 8 edges concurrently. Cross-sub reduce via smem.
// ---------------------------------------------------------------------------
__global__ void __launch_bounds__(128)
spmm_csr_h(const int* __restrict__ rowstart, const int2* __restrict__ edges,
           const __half* __restrict__ h, float* __restrict__ agg)
{
    __shared__ int2 se[128];
    __shared__ float4 part[64][2];
    const int r = blockIdx.x;
    const int t = threadIdx.x;
    const int sub = t >> 6;       // 0 or 1
    const int l = t & 63;         // lane within sub: features [8l, 8l+8)
    const int s = rowstart[r];
    const int e = rowstart[r + 1];
    const uint4* hp = (const uint4*)h;   // row stride = 512*2/16 = 64

    float a0[8], a1[8], a2[8], a3[8];
#pragma unroll
    for (int j = 0; j < 8; j++) { a0[j] = a1[j] = a2[j] = a3[j] = 0.f; }

    auto acc8 = [&](float* a, uint4 d, float v) {
        float2 f0 = __half22float2(*(__half2*)&d.x);
        float2 f1 = __half22float2(*(__half2*)&d.y);
        float2 f2 = __half22float2(*(__half2*)&d.z);
        float2 f3 = __half22float2(*(__half2*)&d.w);
        a[0] += v * f0.x; a[1] += v * f0.y;
        a[2] += v * f1.x; a[3] += v * f1.y;
        a[4] += v * f2.x; a[5] += v * f2.y;
        a[6] += v * f3.x; a[7] += v * f3.y;
    };

    for (int base = s; base < e; base += 128) {
        const int n = min(128, e - base);
        if (t < n) se[t] = __ldg(&edges[base + t]);
        __syncthreads();

        const int half = (n + 1) >> 1;
        const int lo = sub ? half : 0;
        const int hi = sub ? n : half;
        int i = lo;
        for (; i + 4 <= hi; i += 4) {
            int2 e0 = se[i], e1 = se[i + 1], e2 = se[i + 2], e3 = se[i + 3];
            uint4 d0 = __ldg(&hp[(size_t)e0.x * 64 + l]);
            uint4 d1 = __ldg(&hp[(size_t)e1.x * 64 + l]);
            uint4 d2 = __ldg(&hp[(size_t)e2.x * 64 + l]);
            uint4 d3 = __ldg(&hp[(size_t)e3.x * 64 + l]);
            acc8(a0, d0, __int_as_float(e0.y));
            acc8(a1, d1, __int_as_float(e1.y));
            acc8(a2, d2, __int_as_float(e2.y));
            acc8(a3, d3, __int_as_float(e3.y));
        }
        for (; i < hi; i++) {
            int2 e0 = se[i];
            uint4 d0 = __ldg(&hp[(size_t)e0.x * 64 + l]);
            acc8(a0, d0, __int_as_float(e0.y));
        }
        __syncthreads();
    }

    float tot[8];
#pragma unroll
    for (int j = 0; j < 8; j++) tot[j] = (a0[j] + a1[j]) + (a2[j] + a3[j]);

    if (sub) {
        part[l][0] = make_float4(tot[0], tot[1], tot[2], tot[3]);
        part[l][1] = make_float4(tot[4], tot[5], tot[6], tot[7]);
    }
    __syncthreads();
    if (!sub) {
        float4 p0 = part[l][0], p1 = part[l][1];
        float4 o0 = make_float4(tot[0] + p0.x, tot[1] + p0.y, tot[2] + p0.z, tot[3] + p0.w);
        float4 o1 = make_float4(tot[4] + p1.x, tot[5] + p1.y, tot[6] + p1.z, tot[7] + p1.w);
        float* dst = agg + (size_t)r * GRAPH_DIM + l * 8;
        *(float4*)dst = o0;
        *(float4*)(dst + 4) = o1;
    }
}

// ---------------------------------------------------------------------------
// Column statistics + BN coefficient computation
// ---------------------------------------------------------------------------
template <int C>
__global__ void colstats(const float* __restrict__ X, float* __restrict__ stats,
                         int Nrows, int rowsPerBlock)
{
    int col = blockIdx.x * blockDim.x + threadIdx.x;
    if (col >= C) return;
    int r0 = blockIdx.y * rowsPerBlock;
    int r1 = min(r0 + rowsPerBlock, Nrows);
    float s = 0.f, s2 = 0.f;
    for (int r = r0; r < r1; r++) {
        float v = X[(size_t)r * C + col];
        s += v;
        s2 += v * v;
    }
    atomicAdd(&stats[col], s);
    atomicAdd(&stats[C + col], s2);
}

template <int C>
__global__ void bn_coeffs(const float* __restrict__ stats, const float* __restrict__ gamma,
                          const float* __restrict__ beta, float* __restrict__ scale,
                          float* __restrict__ shift, int Nrows)
{
    int c = blockIdx.x * blockDim.x + threadIdx.x;
    if (c >= C) return;
    const float invN = 1.f / (float)Nrows;
    float mean = stats[c] * invN;
    float var = stats[C + c] * invN - mean * mean;
    float sc = rsqrtf(var + BN_EPS) * gamma[c];
    scale[c] = sc;
    shift[c] = beta[c] - mean * sc;
}

// ---------------------------------------------------------------------------
// Launcher
// ---------------------------------------------------------------------------
extern "C" void kernel_launch(void* const* d_in, const int* in_sizes, int n_in,
                              void* d_out, int out_size)
{
    const float* x        = (const float*)d_in[0];
    const int*   adj_rows = (const int*)d_in[1];
    const int*   adj_cols = (const int*)d_in[2];
    const float* adj_vals = (const float*)d_in[3];
    const float* Wg  = (const float*)d_in[4];
    const float* bg  = (const float*)d_in[5];
    const float* W1  = (const float*)d_in[6];
    const float* b1  = (const float*)d_in[7];
    const float* W21 = (const float*)d_in[8];
    const float* b21 = (const float*)d_in[9];
    const float* W22 = (const float*)d_in[10];
    const float* b22 = (const float*)d_in[11];
    const float* gamma0 = (const float*)d_in[12];
    const float* beta0  = (const float*)d_in[13];
    const float* gamma1 = (const float*)d_in[14];
    const float* beta1  = (const float*)d_in[15];
    float* out = (float*)d_out;

    float *agg, *h1, *st0, *st1, *blat, *sc0, *sh0, *sc1, *sh1;
    int *rowcnt, *rowstart, *cursor;
    int2 *edges;
    __half *h16, *wgt, *w1t, *wlat;
    cudaGetSymbolAddress((void**)&h16, g_h16);
    cudaGetSymbolAddress((void**)&agg, g_agg);
    cudaGetSymbolAddress((void**)&h1,  g_h1);
    cudaGetSymbolAddress((void**)&st0, g_stats0);
    cudaGetSymbolAddress((void**)&st1, g_stats1);
    cudaGetSymbolAddress((void**)&blat, g_blat);
    cudaGetSymbolAddress((void**)&sc0, g_sc0);
    cudaGetSymbolAddress((void**)&sh0, g_sh0);
    cudaGetSymbolAddress((void**)&sc1, g_sc1);
    cudaGetSymbolAddress((void**)&sh1, g_sh1);
    cudaGetSymbolAddress((void**)&rowcnt, g_rowcnt);
    cudaGetSymbolAddress((void**)&rowstart, g_rowstart);
    cudaGetSymbolAddress((void**)&cursor, g_cursor);
    cudaGetSymbolAddress((void**)&edges, g_edges);
    cudaGetSymbolAddress((void**)&wgt, g_WgT_f16);
    cudaGetSymbolAddress((void**)&w1t, g_W1T_f16);
    cudaGetSymbolAddress((void**)&wlat, g_WlatT_f16);

    constexpr int SMEM256 = 2 * (ATILE + 256 * RB);  // 110592
    constexpr int SMEM128 = 2 * (ATILE + 128 * RB);  //  73728
    cudaFuncSetAttribute(fp16_gemm<256>, cudaFuncAttributeMaxDynamicSharedMemorySize, SMEM256);
    cudaFuncSetAttribute(fp16_gemm<128>, cudaFuncAttributeMaxDynamicSharedMemorySize, SMEM128);

    // --- launch order keeps GEMM1 as the 4th launch for ncu ---

    // 1-2) stats zero
    zero_kernel<<<1, 256>>>((float4*)st0, 2 * GRAPH_DIM / 4);
    zero_kernel<<<1, 256>>>((float4*)st1, 2 * HIDDEN_DIM / 4);

    // 3) Wg -> fp16 transposed
    {
        int totWg = GRAPH_DIM * IN_DIM_PAD;
        conv_w_fp16<<<cdiv(totWg, 256), 256>>>(Wg, wgt, IN_DIM, GRAPH_DIM, IN_DIM_PAD);
    }

    // 4) GEMM1: h16 = half(x @ Wg + bg)   (fp16, K64 chunks, half2 output)
    {
        dim3 grid(GRAPH_DIM / 256, cdiv(N_NODES, GBM));
        fp16_gemm<256><<<grid, 512, SMEM256>>>(x, IN_DIM, IN_DIM, IN_DIM_PAD,
                                               wgt, bg, h16, GRAPH_DIM, N_NODES,
                                               2, nullptr, nullptr);
    }

    // 5+) CSR build + remaining weight prep
    zero_int<<<cdiv(N_NODES, 256), 256>>>(rowcnt, N_NODES);
    csr_hist<<<cdiv(N_EDGES, 256), 256>>>(adj_rows, rowcnt);
    csr_scan<<<1, 1024>>>(rowcnt, rowstart, cursor);
    csr_scatter<<<cdiv(N_EDGES, 256), 256>>>(adj_rows, adj_cols, adj_vals, cursor, edges);
    {
        int totW1 = HIDDEN_DIM * GRAPH_DIM;
        conv_w_fp16<<<cdiv(totW1, 256), 256>>>(W1, w1t, GRAPH_DIM, HIDDEN_DIM, GRAPH_DIM);
        int totWl = 64 * HIDDEN_DIM;
        conv_w_fp16<<<cdiv(totWl, 256), 256>>>(W21, wlat, HIDDEN_DIM, 64, HIDDEN_DIM);
        conv_w_fp16<<<cdiv(totWl, 256), 256>>>(W22, wlat + (size_t)64 * HIDDEN_DIM,
                                               HIDDEN_DIM, 64, HIDDEN_DIM);
        concat_bias<<<1, 128>>>(b21, b22, blat);
    }

    // SpMM (CSR over half h, uint4 gathers + sub-split)
    spmm_csr_h<<<N_NODES, 128>>>(rowstart, edges, h16, agg);

    // BN0 stats + coefficients
    colstats<GRAPH_DIM><<<dim3(GRAPH_DIM / 256, cdiv(N_NODES, 512)), 256>>>(agg, st0, N_NODES, 512);
    bn_coeffs<GRAPH_DIM><<<GRAPH_DIM / 256, 256>>>(st0, gamma0, beta0, sc0, sh0, N_NODES);

    // GEMM2: h1 = softplus(bn(agg)) @ W1 + b1  (fp16 K64, fused BN0, fp32 out)
    {
        dim3 grid(HIDDEN_DIM / 256, cdiv(N_NODES, GBM));
        fp16_gemm<256><<<grid, 512, SMEM256>>>(agg, GRAPH_DIM, GRAPH_DIM, GRAPH_DIM,
                                               w1t, b1, h1, HIDDEN_DIM, N_NODES,
                                               0, sc0, sh0);
    }

    // BN1 stats + coefficients
    colstats<HIDDEN_DIM><<<dim3(1, cdiv(N_NODES, 512)), 256>>>(h1, st1, N_NODES, 512);
    bn_coeffs<HIDDEN_DIM><<<1, HIDDEN_DIM>>>(st1, gamma1, beta1, sc1, sh1, N_NODES);

    // Latent: [mu | logvar] = softplus(bn(h1)) @ [W21|W22] + blat  (fused BN1)
    {
        dim3 grid(1, cdiv(N_NODES, GBM));
        fp16_gemm<128><<<grid, 512, SMEM128>>>(h1, HIDDEN_DIM, HIDDEN_DIM, HIDDEN_DIM,
                                               wlat, blat, out, 0, N_NODES,
                                               1, sc1, sh1);
    }
    (void)in_sizes; (void)n_in; (void)out_size;
}

// round 15
// speedup vs baseline: 1.0816x; 1.0816x over previous
#include <cuda_runtime.h>
#include <cuda_bf16.h>
#include <cuda_fp16.h>
#include <cstdint>

#define N_NODES 50000
#define IN_DIM 2000
#define IN_DIM_PAD 2048
#define GRAPH_DIM 512
#define HIDDEN_DIM 256
#define LATENT_DIM 64
#define N_EDGES 1600000
#define BN_EPS 1e-5f

// Scratch (device globals; allocation is forbidden)
__device__ __half g_h16[(size_t)N_NODES * GRAPH_DIM];
__device__ float g_agg[(size_t)N_NODES * GRAPH_DIM];
__device__ float g_h1[(size_t)N_NODES * HIDDEN_DIM];
__device__ float g_stats0[2 * GRAPH_DIM];
__device__ float g_stats1[2 * HIDDEN_DIM];
__device__ float g_sc0[GRAPH_DIM], g_sh0[GRAPH_DIM];
__device__ float g_sc1[HIDDEN_DIM], g_sh1[HIDDEN_DIM];
// CSR scratch
__device__ int g_rowcnt[N_NODES];
__device__ int g_rowstart[N_NODES + 1];
__device__ int g_cursor[N_NODES];
__device__ int2 g_edges[N_EDGES];
// fp16 transposed weights
__device__ __half g_WgT_f16[(size_t)GRAPH_DIM * IN_DIM_PAD];
__device__ __half g_W1T_f16[(size_t)HIDDEN_DIM * GRAPH_DIM];
__device__ __half g_WlatT_f16[(size_t)128 * HIDDEN_DIM];
__device__ float g_blat[128];

static inline int cdiv(int a, int b) { return (a + b - 1) / b; }

// ---------------------------------------------------------------------------
// PTX helpers
// ---------------------------------------------------------------------------
__device__ __forceinline__ uint32_t smem_u32(const void* p) {
    uint32_t a;
    asm("{ .reg .u64 t; cvta.to.shared.u64 t, %1; cvt.u32.u64 %0, t; }" : "=r"(a) : "l"(p));
    return a;
}
__device__ __forceinline__ void ldsm4(uint32_t* d, uint32_t addr) {
    asm volatile("ldmatrix.sync.aligned.m8n8.x4.shared.b16 {%0,%1,%2,%3}, [%4];"
                 : "=r"(d[0]), "=r"(d[1]), "=r"(d[2]), "=r"(d[3]) : "r"(addr));
}
__device__ __forceinline__ void mma_fp16(float* c, const uint32_t* a, const uint32_t* b) {
    asm volatile(
        "mma.sync.aligned.m16n8k16.row.col.f32.f16.f16.f32 "
        "{%0,%1,%2,%3}, {%4,%5,%6,%7}, {%8,%9}, {%0,%1,%2,%3};"
        : "+f"(c[0]), "+f"(c[1]), "+f"(c[2]), "+f"(c[3])
        : "r"(a[0]), "r"(a[1]), "r"(a[2]), "r"(a[3]), "r"(b[0]), "r"(b[1]));
}
__device__ __forceinline__ void cp16(uint32_t dst, const void* src) {
    asm volatile("cp.async.cg.shared.global [%0], [%1], 16;" :: "r"(dst), "l"(src));
}
#define CP_COMMIT() asm volatile("cp.async.commit_group;" ::: "memory")
#define CP_WAIT0()  asm volatile("cp.async.wait_group 0;" ::: "memory")

__device__ __forceinline__ uint32_t pack_h2(__half lo, __half hi) {
    return ((uint32_t)__half_as_ushort(hi) << 16) | (uint32_t)__half_as_ushort(lo);
}
__device__ __forceinline__ float softplus_f(float x) {
    return fmaxf(x, 0.f) + log1pf(expf(-fabsf(x)));
}

// ---------------------------------------------------------------------------
// Weight prep: W[K,Nc] fp32 -> T[Nc][Kpad] fp16 (transposed)
// ---------------------------------------------------------------------------
__global__ void conv_w_fp16(const float* __restrict__ W, __half* __restrict__ T,
                            int K, int Nc, int Kpad)
{
    int idx = blockIdx.x * blockDim.x + threadIdx.x;
    if (idx >= Nc * Kpad) return;
    int n = idx / Kpad;
    int k = idx % Kpad;
    float v = (k < K) ? W[(size_t)k * Nc + n] : 0.f;
    T[idx] = __float2half(v);
}

__global__ void concat_bias(const float* __restrict__ b21, const float* __restrict__ b22,
                            float* __restrict__ blat)
{
    int t = threadIdx.x;
    if (t < 64) blat[t] = b21[t];
    else if (t < 128) blat[t] = b22[t - 64];
}

// ---------------------------------------------------------------------------
// fp16 tensor-core GEMM, K-chunk 64, 512 threads (16 warps, warptile 32 x BN/4).
// ---------------------------------------------------------------------------
#define GBM 128
#define GK 64
#define RB 144
#define ATILE (GBM * RB)   // 18432

template <int BN>
__global__ void __launch_bounds__(512)
fp16_gemm(const float* __restrict__ A, int lda, int Kvalid, int Kpad,
          const __half* __restrict__ B,
          const float* __restrict__ bias, void* __restrict__ Cv, int ldc, int M,
          int outmode, const float* __restrict__ Ascale, const float* __restrict__ Ashift)
{
    constexpr int BTILE = BN * RB;
    constexpr int STAGE = ATILE + BTILE;
    constexpr int NT = BN / 32;
    constexpr int NLD = BN / 64;
    constexpr int BCH = BN * GK / 4096;

    extern __shared__ char sm[];
    const uint32_t smb = smem_u32(sm);

    const int tid = threadIdx.x;
    const int lane = tid & 31;
    const int wid = tid >> 5;
    const int warpM = wid >> 2;
    const int warpN = wid & 3;
    const int rowBase = blockIdx.y * GBM;
    const int colBase = blockIdx.x * BN;
    const int nIter = Kpad / GK;
    const bool fuse = (Ascale != nullptr);

    float acc[2][NT][4];
#pragma unroll
    for (int i = 0; i < 2; i++)
#pragma unroll
        for (int j = 0; j < NT; j++)
#pragma unroll
            for (int v = 0; v < 4; v++) acc[i][j][v] = 0.f;

    float4 av[4];
    int arow[4], akq[4];
#pragma unroll
    for (int q = 0; q < 4; q++) {
        int qi = tid + q * 512;
        arow[q] = qi >> 4;
        akq[q] = qi & 15;
    }

    auto loadA = [&](int it) {
        int k0 = it * GK;
#pragma unroll
        for (int q = 0; q < 4; q++) {
            int gr = rowBase + arow[q];
            int k = k0 + akq[q] * 4;
            float4 v = make_float4(0.f, 0.f, 0.f, 0.f);
            if (gr < M) {
                const float* src = A + (size_t)gr * lda + k;
                if (k + 3 < Kvalid) {
                    v = *(const float4*)src;
                    if (fuse) {
                        v.x = softplus_f(v.x * __ldg(&Ascale[k + 0]) + __ldg(&Ashift[k + 0]));
                        v.y = softplus_f(v.y * __ldg(&Ascale[k + 1]) + __ldg(&Ashift[k + 1]));
                        v.z = softplus_f(v.z * __ldg(&Ascale[k + 2]) + __ldg(&Ashift[k + 2]));
                        v.w = softplus_f(v.w * __ldg(&Ascale[k + 3]) + __ldg(&Ashift[k + 3]));
                    }
                } else if (k < Kvalid) {
                    float* vp = &v.x;
#pragma unroll
                    for (int j = 0; j < 4; j++) {
                        if (k + j < Kvalid) {
                            float t = src[j];
                            if (fuse)
                                t = softplus_f(t * __ldg(&Ascale[k + j]) + __ldg(&Ashift[k + j]));
                            vp[j] = t;
                        }
                    }
                }
            }
            av[q] = v;
        }
    };

    auto stsA = [&](int stage) {
        char* sp = sm + stage * STAGE;
#pragma unroll
        for (int q = 0; q < 4; q++) {
            float4 v = av[q];
            __half h0 = __float2half(v.x);
            __half h1 = __float2half(v.y);
            __half h2 = __float2half(v.z);
            __half h3 = __float2half(v.w);
            uint2 hp = make_uint2(pack_h2(h0, h1), pack_h2(h2, h3));
            int off = arow[q] * RB + akq[q] * 8;
            *(uint2*)(sp + off) = hp;
        }
    };

    auto cpB = [&](int it, int stage) {
        int k0 = it * GK;
#pragma unroll
        for (int q = 0; q < BCH; q++) {
            int ci = tid + q * 512;
            int row = ci >> 3;
            int c = ci & 7;
            const __half* src = B + (size_t)(colBase + row) * Kpad + k0 + c * 8;
            uint32_t dst = smb + stage * STAGE + ATILE + row * RB + c * 16;
            cp16(dst, src);
        }
    };

    const uint32_t aLaneOff = (uint32_t)((lane & 15) * RB + ((lane >> 4) << 4));
    const uint32_t bLaneOff = (uint32_t)(((lane & 7) + ((lane & 16) >> 1)) * RB
                                         + (((lane >> 3) & 1) << 4));

    loadA(0);
    cpB(0, 0);
    CP_COMMIT();
    stsA(0);

    for (int it = 0; it < nIter; ++it) {
        const int cur = it & 1;
        const int nxt = cur ^ 1;
        const bool more = (it + 1 < nIter);
        if (more) loadA(it + 1);
        CP_WAIT0();
        __syncthreads();
        if (more) {
            stsA(nxt);
            cpB(it + 1, nxt);
            CP_COMMIT();
        }

        const uint32_t aBase = smb + cur * STAGE + warpM * 32 * RB + aLaneOff;
        const uint32_t bBase = smb + cur * STAGE + ATILE + warpN * (BN / 4) * RB + bLaneOff;
#pragma unroll
        for (int ks = 0; ks < GK / 16; ks++) {
            const uint32_t kb = ks * 32;
            uint32_t bF[NLD][4], aH[2][4];
#pragma unroll
            for (int g = 0; g < NLD; g++) ldsm4(bF[g], bBase + g * 16 * RB + kb);
#pragma unroll
            for (int mt = 0; mt < 2; mt++) ldsm4(aH[mt], aBase + mt * 16 * RB + kb);
#pragma unroll
            for (int mt = 0; mt < 2; mt++)
#pragma unroll
                for (int nt = 0; nt < NT; nt++)
                    mma_fp16(acc[mt][nt], aH[mt], &bF[nt >> 1][(nt & 1) * 2]);
        }
    }

    const int r0 = rowBase + warpM * 32 + (lane >> 2);
    const int c0 = colBase + warpN * (BN / 4) + (lane & 3) * 2;
#pragma unroll
    for (int mt = 0; mt < 2; mt++) {
#pragma unroll
        for (int nt = 0; nt < NT; nt++) {
            int r = r0 + mt * 16;
            int c = c0 + nt * 8;
            float b0 = bias[c], b1 = bias[c + 1];
            float v0 = acc[mt][nt][0] + b0;
            float v1 = acc[mt][nt][1] + b1;
            float v2 = acc[mt][nt][2] + b0;
            float v3 = acc[mt][nt][3] + b1;
            if (outmode == 0) {
                float* C = (float*)Cv;
                if (r < M) *(float2*)&C[(size_t)r * ldc + c] = make_float2(v0, v1);
                if (r + 8 < M) *(float2*)&C[(size_t)(r + 8) * ldc + c] = make_float2(v2, v3);
            } else if (outmode == 1) {
                float* C = (float*)Cv;
                float* base = (c < 64) ? C + c : C + (size_t)N_NODES * 64 + (c - 64);
                if (r < M) *(float2*)&base[(size_t)r * 64] = make_float2(v0, v1);
                if (r + 8 < M) *(float2*)&base[(size_t)(r + 8) * 64] = make_float2(v2, v3);
            } else {
                __half* C = (__half*)Cv;
                if (r < M) *(__half2*)&C[(size_t)r * ldc + c] = __floats2half2_rn(v0, v1);
                if (r + 8 < M) *(__half2*)&C[(size_t)(r + 8) * ldc + c] = __floats2half2_rn(v2, v3);
            }
        }
    }
}

// ---------------------------------------------------------------------------
// Zero kernels
// ---------------------------------------------------------------------------
__global__ void zero_kernel(float4* __restrict__ p, long long n4) {
    long long i = (long long)blockIdx.x * blockDim.x + threadIdx.x;
    long long stride = (long long)gridDim.x * blockDim.x;
    float4 z = make_float4(0.f, 0.f, 0.f, 0.f);
    for (; i < n4; i += stride) p[i] = z;
}
__global__ void zero_int(int* __restrict__ p, int n) {
    int i = blockIdx.x * blockDim.x + threadIdx.x;
    if (i < n) p[i] = 0;
}

// ---------------------------------------------------------------------------
// CSR build: histogram -> scan -> scatter
// ---------------------------------------------------------------------------
__global__ void csr_hist(const int* __restrict__ rows, int* __restrict__ cnt) {
    int e = blockIdx.x * blockDim.x + threadIdx.x;
    if (e < N_EDGES) atomicAdd(&cnt[rows[e]], 1);
}

__global__ void __launch_bounds__(1024)
csr_scan(const int* __restrict__ cnt, int* __restrict__ rowstart, int* __restrict__ cursor)
{
    __shared__ int warpsum[32];
    const int t = threadIdx.x;
    const int CH = (N_NODES + 1023) / 1024;
    const int base = t * CH;

    int s = 0;
    for (int i = 0; i < CH; i++) {
        int idx = base + i;
        if (idx < N_NODES) s += cnt[idx];
    }
    int lane = t & 31, w = t >> 5;
    int v = s;
#pragma unroll
    for (int o = 1; o < 32; o <<= 1) {
        int n = __shfl_up_sync(0xffffffffu, v, o);
        if (lane >= o) v += n;
    }
    if (lane == 31) warpsum[w] = v;
    __syncthreads();
    if (w == 0) {
        int x = warpsum[lane];
#pragma unroll
        for (int o = 1; o < 32; o <<= 1) {
            int n = __shfl_up_sync(0xffffffffu, x, o);
            if (lane >= o) x += n;
        }
        warpsum[lane] = x;
    }
    __syncthreads();
    int run = v - s + (w > 0 ? warpsum[w - 1] : 0);
    for (int i = 0; i < CH; i++) {
        int idx = base + i;
        if (idx < N_NODES) {
            rowstart[idx] = run;
            cursor[idx] = run;
            run += cnt[idx];
        }
    }
    if (t == 1023) rowstart[N_NODES] = N_EDGES;
}

__global__ void csr_scatter(const int* __restrict__ rows, const int* __restrict__ cols,
                            const float* __restrict__ vals, int* __restrict__ cursor,
                            int2* __restrict__ edges)
{
    int e = blockIdx.x * blockDim.x + threadIdx.x;
    if (e >= N_EDGES) return;
    int r = rows[e];
    int p = atomicAdd(&cursor[r], 1);
    edges[p] = make_int2(cols[e], __float_as_int(vals[e]));
}

// ---------------------------------------------------------------------------
// CSR SpMM over half h (R13 version): smem-staged edges, 4-deep uint2 gathers.
// ---------------------------------------------------------------------------
__global__ void __launch_bounds__(128)
spmm_csr_h(const int* __restrict__ rowstart, const int2* __restrict__ edges,
           const __half* __restrict__ h, float* __restrict__ agg)
{
    __shared__ int2 se[128];
    const int r = blockIdx.x;
    const int t = threadIdx.x;
    const int s = rowstart[r];
    const int e = rowstart[r + 1];

    float4 a0 = make_float4(0.f, 0.f, 0.f, 0.f);
    float4 a1 = make_float4(0.f, 0.f, 0.f, 0.f);
    float4 a2 = make_float4(0.f, 0.f, 0.f, 0.f);
    float4 a3 = make_float4(0.f, 0.f, 0.f, 0.f);

    auto fetch = [&](int col) -> float4 {
        uint2 d = __ldg((const uint2*)(h + (size_t)col * GRAPH_DIM) + t);
        float2 p0 = __half22float2(*(__half2*)&d.x);
        float2 p1 = __half22float2(*(__half2*)&d.y);
        return make_float4(p0.x, p0.y, p1.x, p1.y);
    };

    for (int base = s; base < e; base += 128) {
        const int n = min(128, e - base);
        if (t < n) se[t] = __ldg(&edges[base + t]);
        __syncthreads();

        int i = 0;
        for (; i + 4 <= n; i += 4) {
            int2 e0 = se[i], e1 = se[i + 1], e2 = se[i + 2], e3 = se[i + 3];
            float4 h0 = fetch(e0.x);
            float4 h1 = fetch(e1.x);
            float4 h2 = fetch(e2.x);
            float4 h3 = fetch(e3.x);
            float v0 = __int_as_float(e0.y), v1 = __int_as_float(e1.y);
            float v2 = __int_as_float(e2.y), v3 = __int_as_float(e3.y);
            a0.x += v0 * h0.x; a0.y += v0 * h0.y; a0.z += v0 * h0.z; a0.w += v0 * h0.w;
            a1.x += v1 * h1.x; a1.y += v1 * h1.y; a1.z += v1 * h1.z; a1.w += v1 * h1.w;
            a2.x += v2 * h2.x; a2.y += v2 * h2.y; a2.z += v2 * h2.z; a2.w += v2 * h2.w;
            a3.x += v3 * h3.x; a3.y += v3 * h3.y; a3.z += v3 * h3.z; a3.w += v3 * h3.w;
        }
        for (; i < n; i++) {
            int2 e0 = se[i];
            float4 h0 = fetch(e0.x);
            float v0 = __int_as_float(e0.y);
            a0.x += v0 * h0.x; a0.y += v0 * h0.y; a0.z += v0 * h0.z; a0.w += v0 * h0.w;
        }
        __syncthreads();
    }

    float4 o;
    o.x = (a0.x + a1.x) + (a2.x + a3.x);
    o.y = (a0.y + a1.y) + (a2.y + a3.y);
    o.z = (a0.z + a1.z) + (a2.z + a3.z);
    o.w = (a0.w + a1.w) + (a2.w + a3.w);
    ((float4*)agg)[(size_t)r * 128 + t] = o;
}

// ---------------------------------------------------------------------------
// Column statistics + BN coefficient computation
// ---------------------------------------------------------------------------
template <int C>
__global__ void colstats(const float* __restrict__ X, float* __restrict__ stats,
                         int Nrows, int rowsPerBlock)
{
    int col = blockIdx.x * blockDim.x + threadIdx.x;
    if (col >= C) return;
    int r0 = blockIdx.y * rowsPerBlock;
    int r1 = min(r0 + rowsPerBlock, Nrows);
    float s = 0.f, s2 = 0.f;
    for (int r = r0; r < r1; r++) {
        float v = X[(size_t)r * C + col];
        s += v;
        s2 += v * v;
    }
    atomicAdd(&stats[col], s);
    atomicAdd(&stats[C + col], s2);
}

template <int C>
__global__ void bn_coeffs(const float* __restrict__ stats, const float* __restrict__ gamma,
                          const float* __restrict__ beta, float* __restrict__ scale,
                          float* __restrict__ shift, int Nrows)
{
    int c = blockIdx.x * blockDim.x + threadIdx.x;
    if (c >= C) return;
    const float invN = 1.f / (float)Nrows;
    float mean = stats[c] * invN;
    float var = stats[C + c] * invN - mean * mean;
    float sc = rsqrtf(var + BN_EPS) * gamma[c];
    scale[c] = sc;
    shift[c] = beta[c] - mean * sc;
}

// ---------------------------------------------------------------------------
// Launcher (dual-stream: CSR build + prep overlapped with GEMM1)
// ---------------------------------------------------------------------------
extern "C" void kernel_launch(void* const* d_in, const int* in_sizes, int n_in,
                              void* d_out, int out_size)
{
    const float* x        = (const float*)d_in[0];
    const int*   adj_rows = (const int*)d_in[1];
    const int*   adj_cols = (const int*)d_in[2];
    const float* adj_vals = (const float*)d_in[3];
    const float* Wg  = (const float*)d_in[4];
    const float* bg  = (const float*)d_in[5];
    const float* W1  = (const float*)d_in[6];
    const float* b1  = (const float*)d_in[7];
    const float* W21 = (const float*)d_in[8];
    const float* b21 = (const float*)d_in[9];
    const float* W22 = (const float*)d_in[10];
    const float* b22 = (const float*)d_in[11];
    const float* gamma0 = (const float*)d_in[12];
    const float* beta0  = (const float*)d_in[13];
    const float* gamma1 = (const float*)d_in[14];
    const float* beta1  = (const float*)d_in[15];
    float* out = (float*)d_out;

    float *agg, *h1, *st0, *st1, *blat, *sc0, *sh0, *sc1, *sh1;
    int *rowcnt, *rowstart, *cursor;
    int2 *edges;
    __half *h16, *wgt, *w1t, *wlat;
    cudaGetSymbolAddress((void**)&h16, g_h16);
    cudaGetSymbolAddress((void**)&agg, g_agg);
    cudaGetSymbolAddress((void**)&h1,  g_h1);
    cudaGetSymbolAddress((void**)&st0, g_stats0);
    cudaGetSymbolAddress((void**)&st1, g_stats1);
    cudaGetSymbolAddress((void**)&blat, g_blat);
    cudaGetSymbolAddress((void**)&sc0, g_sc0);
    cudaGetSymbolAddress((void**)&sh0, g_sh0);
    cudaGetSymbolAddress((void**)&sc1, g_sc1);
    cudaGetSymbolAddress((void**)&sh1, g_sh1);
    cudaGetSymbolAddress((void**)&rowcnt, g_rowcnt);
    cudaGetSymbolAddress((void**)&rowstart, g_rowstart);
    cudaGetSymbolAddress((void**)&cursor, g_cursor);
    cudaGetSymbolAddress((void**)&edges, g_edges);
    cudaGetSymbolAddress((void**)&wgt, g_WgT_f16);
    cudaGetSymbolAddress((void**)&w1t, g_W1T_f16);
    cudaGetSymbolAddress((void**)&wlat, g_WlatT_f16);

    constexpr int SMEM256 = 2 * (ATILE + 256 * RB);  // 110592
    constexpr int SMEM128 = 2 * (ATILE + 128 * RB);  //  73728
    cudaFuncSetAttribute(fp16_gemm<256>, cudaFuncAttributeMaxDynamicSharedMemorySize, SMEM256);
    cudaFuncSetAttribute(fp16_gemm<128>, cudaFuncAttributeMaxDynamicSharedMemorySize, SMEM128);

    // Static side stream + events (host objects; same work every call).
    static cudaStream_t s2 = nullptr;
    static cudaEvent_t evFork = nullptr, evJoin = nullptr;
    if (!s2) {
        cudaStreamCreateWithFlags(&s2, cudaStreamNonBlocking);
        cudaEventCreateWithFlags(&evFork, cudaEventDisableTiming);
        cudaEventCreateWithFlags(&evJoin, cudaEventDisableTiming);
    }

    // --- fork: side stream does CSR build + prep independent of GEMM1 ---
    cudaEventRecord(evFork, 0);
    cudaStreamWaitEvent(s2, evFork, 0);

    // Side stream (s2): stats zero, CSR build, W1/Wlat prep
    zero_kernel<<<1, 256, 0, s2>>>((float4*)st0, 2 * GRAPH_DIM / 4);
    zero_kernel<<<1, 256, 0, s2>>>((float4*)st1, 2 * HIDDEN_DIM / 4);
    zero_int<<<cdiv(N_NODES, 256), 256, 0, s2>>>(rowcnt, N_NODES);
    csr_hist<<<cdiv(N_EDGES, 256), 256, 0, s2>>>(adj_rows, rowcnt);
    csr_scan<<<1, 1024, 0, s2>>>(rowcnt, rowstart, cursor);
    csr_scatter<<<cdiv(N_EDGES, 256), 256, 0, s2>>>(adj_rows, adj_cols, adj_vals, cursor, edges);
    {
        int totW1 = HIDDEN_DIM * GRAPH_DIM;
        conv_w_fp16<<<cdiv(totW1, 256), 256, 0, s2>>>(W1, w1t, GRAPH_DIM, HIDDEN_DIM, GRAPH_DIM);
        int totWl = 64 * HIDDEN_DIM;
        conv_w_fp16<<<cdiv(totWl, 256), 256, 0, s2>>>(W21, wlat, HIDDEN_DIM, 64, HIDDEN_DIM);
        conv_w_fp16<<<cdiv(totWl, 256), 256, 0, s2>>>(W22, wlat + (size_t)64 * HIDDEN_DIM,
                                                      HIDDEN_DIM, 64, HIDDEN_DIM);
        concat_bias<<<1, 128, 0, s2>>>(b21, b22, blat);
    }
    cudaEventRecord(evJoin, s2);

    // Main stream: Wg prep + GEMM1 (tensor-bound; co-runs with s2's memory work)
    {
        int totWg = GRAPH_DIM * IN_DIM_PAD;
        conv_w_fp16<<<cdiv(totWg, 256), 256>>>(Wg, wgt, IN_DIM, GRAPH_DIM, IN_DIM_PAD);
    }
    {
        dim3 grid(GRAPH_DIM / 256, cdiv(N_NODES, GBM));
        fp16_gemm<256><<<grid, 512, SMEM256>>>(x, IN_DIM, IN_DIM, IN_DIM_PAD,
                                               wgt, bg, h16, GRAPH_DIM, N_NODES,
                                               2, nullptr, nullptr);
    }

    // --- join: SpMM needs h16 (main) + edges (s2) ---
    cudaStreamWaitEvent(0, evJoin, 0);

    // SpMM (CSR over half h)
    spmm_csr_h<<<N_NODES, 128>>>(rowstart, edges, h16, agg);

    // BN0 stats + coefficients
    colstats<GRAPH_DIM><<<dim3(GRAPH_DIM / 256, cdiv(N_NODES, 512)), 256>>>(agg, st0, N_NODES, 512);
    bn_coeffs<GRAPH_DIM><<<GRAPH_DIM / 256, 256>>>(st0, gamma0, beta0, sc0, sh0, N_NODES);

    // GEMM2: h1 = softplus(bn(agg)) @ W1 + b1  (fp16 K64, fused BN0, fp32 out)
    {
        dim3 grid(HIDDEN_DIM / 256, cdiv(N_NODES, GBM));
        fp16_gemm<256><<<grid, 512, SMEM256>>>(agg, GRAPH_DIM, GRAPH_DIM, GRAPH_DIM,
                                               w1t, b1, h1, HIDDEN_DIM, N_NODES,
                                               0, sc0, sh0);
    }

    // BN1 stats + coefficients
    colstats<HIDDEN_DIM><<<dim3(1, cdiv(N_NODES, 512)), 256>>>(h1, st1, N_NODES, 512);
    bn_coeffs<HIDDEN_DIM><<<1, HIDDEN_DIM>>>(st1, gamma1, beta1, sc1, sh1, N_NODES);

    // Latent: [mu | logvar] = softplus(bn(h1)) @ [W21|W22] + blat  (fused BN1)
    {
        dim3 grid(1, cdiv(N_NODES, GBM));
        fp16_gemm<128><<<grid, 512, SMEM128>>>(h1, HIDDEN_DIM, HIDDEN_DIM, HIDDEN_DIM,
                                               wlat, blat, out, 0, N_NODES,
                                               1, sc1, sh1);
    }
    (void)in_sizes; (void)n_in; (void)out_size;
}